// round 7
// baseline (speedup 1.0000x reference)
#include <cuda_runtime.h>
#include <stdint.h>

#define BB   8
#define NN   4096
#define CPN  57
#define KK   16
#define THR  0.04f
#define NC   125
#define NBIN 64
#define TCAP 20

// ---------------- scratch (device globals; no allocation allowed) -----------
__device__ int2   g_knn_pair[BB * NN * KK];   // (idx, dist bits) interleaved
__device__ int    g_off[BB * 128];
__device__ float4 g_sx[BB * NN];
__device__ int    g_sj[BB * NN];
__device__ float  g_h67[BB * NN * 68];        // [agg(64) | xyz(3) | pad]

// ---------------------------------------------------------------------------
// f32x2 packed helpers
// ---------------------------------------------------------------------------
typedef unsigned long long u64;
__device__ __forceinline__ u64 f2pack(float a, float b) {
    u64 r; asm("mov.b64 %0,{%1,%2};" : "=l"(r) : "f"(a), "f"(b)); return r;
}
__device__ __forceinline__ void f2unpack(u64 v, float& a, float& b) {
    asm("mov.b64 {%0,%1},%2;" : "=f"(a), "=f"(b) : "l"(v));
}
__device__ __forceinline__ u64 ffma2(u64 a, u64 b, u64 c) {
    u64 d; asm("fma.rn.f32x2 %0,%1,%2,%3;" : "=l"(d) : "l"(a), "l"(b), "l"(c));
    return d;
}
__device__ __forceinline__ void lds2x64(u64& a, u64& b, unsigned addr) {
    asm volatile("ld.shared.v2.b64 {%0,%1},[%2];"
                 : "=l"(a), "=l"(b) : "r"(addr));
}

// ---------------------------------------------------------------------------
// Fused grid build: one block per batch.  count -> scan -> scatter in SMEM.
// ---------------------------------------------------------------------------
__device__ __forceinline__ int cell_of(float x, float y, float z) {
    int cx = min((int)(x * 5.0f), 4);
    int cy = min((int)(y * 5.0f), 4);
    int cz = min((int)(z * 5.0f), 4);
    return (cx * 5 + cy) * 5 + cz;
}

__global__ void grid_build(const float* __restrict__ xyz) {
    __shared__ int scnt[NC];
    __shared__ int soff[NC + 1];
    __shared__ int scur[NC];
    const int b = blockIdx.x;
    const float* bx = xyz + (size_t)b * NN * 3;

    for (int t = threadIdx.x; t < NC; t += 512) scnt[t] = 0;
    __syncthreads();

    for (int i = threadIdx.x; i < NN; i += 512) {
        float x = bx[i * 3 + 0], y = bx[i * 3 + 1], z = bx[i * 3 + 2];
        atomicAdd(&scnt[cell_of(x, y, z)], 1);
    }
    __syncthreads();

    if (threadIdx.x == 0) {
        int acc = 0;
        for (int c = 0; c < NC; c++) { soff[c] = acc; scur[c] = acc; acc += scnt[c]; }
        soff[NC] = acc;
    }
    __syncthreads();

    for (int t = threadIdx.x; t <= NC; t += 512) g_off[b * 128 + t] = soff[t];

    for (int i = threadIdx.x; i < NN; i += 512) {
        float x = bx[i * 3 + 0], y = bx[i * 3 + 1], z = bx[i * 3 + 2];
        int cell = cell_of(x, y, z);
        int pos = atomicAdd(&scur[cell], 1);
        float sq = fmaf(z, z, fmaf(y, y, x * x));
        g_sx[(b << 12) + pos] = make_float4(x, y, z, sq);
        g_sj[(b << 12) + pos] = i;
    }
}

// ---------------------------------------------------------------------------
// kNN query: histogram two-pass selection (unchanged from R6).
// ---------------------------------------------------------------------------
#define KNN_SCAN(BODY)                                                        \
    for (int dx = -1; dx <= 1; dx++) {                                        \
        int ncx = cx + dx; if (ncx < 0 || ncx > 4) continue;                  \
        for (int dy = -1; dy <= 1; dy++) {                                    \
            int ncy = cy + dy; if (ncy < 0 || ncy > 4) continue;              \
            int cb2 = b * 128 + (ncx * 5 + ncy) * 5;                          \
            int sbeg = g_off[cb2 + czlo];                                     \
            int send = g_off[cb2 + czhi + 1];                                 \
            for (int s = sbeg; s < send; s++) {                               \
                float4 c = g_sx[(b << 12) + s];                               \
                float dot = fmaf(q.z, c.z, fmaf(q.y, c.y, q.x * c.x));        \
                float rhs = fmaf(0.5f, c.w, qoff);                            \
                if (dot >= rhs) {                                             \
                    float t1 = qsq + c.w;                                     \
                    float d = __fsub_rn(t1, __fmul_rn(2.0f, dot));            \
                    if (d <= THR) { BODY }                                    \
                }                                                             \
            }                                                                 \
        }                                                                     \
    }

__global__ __launch_bounds__(128) void knn_query() {
    __shared__ unsigned short hist[NBIN * 128];
    __shared__ int2 tl[128 * TCAP];
    const int tid = threadIdx.x;
    const int b = blockIdx.y;
    const int slot = blockIdx.x * 128 + tid;
    const float4 q = g_sx[(b << 12) + slot];
    const int qi = g_sj[(b << 12) + slot];
    const float qsq = q.w;
    const int cx = min((int)(q.x * 5.0f), 4);
    const int cy = min((int)(q.y * 5.0f), 4);
    const int cz = min((int)(q.z * 5.0f), 4);
    const float qoff = 0.5f * (qsq - THR) - 1e-5f;
    const int czlo = max(cz - 1, 0), czhi = min(cz + 1, 4);

#pragma unroll 8
    for (int bn = 0; bn < NBIN; bn++) hist[bn * 128 + tid] = 0;

    // ---- pass A: histogram of exact d -----------------------------------
    KNN_SCAN({
        int bn = max(0, min(NBIN - 1, (int)(d * 1600.0f)));   // 64 / 0.04
        hist[bn * 128 + tid]++;
    })

    // ---- threshold: smallest bin with cum >= K --------------------------
    int tstar = NBIN, cum = 0;
#pragma unroll 8
    for (int bn = 0; bn < NBIN; bn++) {
        int c = (int)hist[bn * 128 + tid];
        if (tstar == NBIN && cum + c >= KK) tstar = bn;
        cum += c;
    }

    const int base = (b * NN + qi) * KK;
    int cnt = 0, tcnt = 0;

    // ---- pass B: direct-stream + threshold list -------------------------
    KNN_SCAN({
        int bn = max(0, min(NBIN - 1, (int)(d * 1600.0f)));
        if (bn < tstar) {
            int j = g_sj[(b << 12) + s];
            g_knn_pair[base + cnt] =
                make_int2(j, __float_as_int(fmaxf(d, 0.0f)));
            cnt++;
        } else if (bn == tstar && tcnt < TCAP) {
            int j = g_sj[(b << 12) + s];
            tl[tid * TCAP + tcnt] = make_int2(j, __float_as_int(d));
            tcnt++;
        }
    })

    // ---- resolve threshold bin by exact (d, j) lexicographic order ------
    if (tstar < NBIN) {
        int need = KK - cnt;
        if (need > tcnt) need = tcnt;
        for (int s2 = 0; s2 < need; s2++) {
            float bd = 3.0e38f; int bj = 0x7fffffff, bi = -1;
            for (int i2 = 0; i2 < tcnt; i2++) {
                int2 e = tl[tid * TCAP + i2];
                float dv = __int_as_float(e.y);
                bool g = (dv < bd) || (dv == bd && e.x < bj);
                if (g) { bd = dv; bj = e.x; bi = i2; }
            }
            tl[tid * TCAP + bi].y = __float_as_int(3.0e38f);
            g_knn_pair[base + cnt] =
                make_int2(bj, __float_as_int(fmaxf(bd, 0.0f)));
            cnt++;
        }
    }
    for (; cnt < KK; cnt++) g_knn_pair[base + cnt] = make_int2(qi, 0);
}

// ============================================================================
// dfg kernel: W1/W2 in SMEM (18.7KB) + 8 warps x 5.2KB hidT = 60KB.
// __launch_bounds__(256,3): cap regs at 85 so 3 blocks (24 warps/SM) fit.
// ============================================================================
#define DW    8
#define DPPW  8
#define DTPB  (DW * 32)

#define D_W1  0
#define D_B1  448
#define D_W2  512
#define D_B2  4608
#define D_SCR 4672
#define D_WS  1296
#define DSMEM_FLOATS (D_SCR + DW * D_WS)
#define DSMEM_BYTES  (DSMEM_FLOATS * 4)

__global__ __launch_bounds__(DTPB, 3)
void dfg_kernel(const float* __restrict__ xyz,
                const float* __restrict__ points,
                const float* __restrict__ w1, const float* __restrict__ b1,
                const float* __restrict__ w2, const float* __restrict__ b2) {
    extern __shared__ float sm[];

    for (int t = threadIdx.x; t < 448; t += DTPB)  sm[D_W1 + t] = w1[t];
    for (int t = threadIdx.x; t < 64;  t += DTPB)  sm[D_B1 + t] = b1[t];
    for (int t = threadIdx.x; t < 4096; t += DTPB) sm[D_W2 + t] = w2[t];
    for (int t = threadIdx.x; t < 64;  t += DTPB)  sm[D_B2 + t] = b2[t];
    __syncthreads();

    const int warp = threadIdx.x >> 5;
    const int lane = threadIdx.x & 31;
    const int c0 = 2 * lane, c1 = c0 + 1;

    float w1r0[7], w1r1[7];
#pragma unroll
    for (int t = 0; t < 7; t++) {
        w1r0[t] = sm[D_W1 + t * 64 + c0];
        w1r1[t] = sm[D_W1 + t * 64 + c1];
    }
    const float lb10 = sm[D_B1 + c0], lb11 = sm[D_B1 + c1];
    const float lb20 = sm[D_B2 + c0], lb21 = sm[D_B2 + c1];

    float* ws = sm + D_SCR + warp * D_WS;
    const unsigned hidT32 =
        (unsigned)__cvta_generic_to_shared(sm) +
        (unsigned)(D_SCR + warp * D_WS) * 4u;

#pragma unroll 1
    for (int pp = 0; pp < DPPW; pp++) {
        const int p = blockIdx.x * (DW * DPPW) + warp * DPPW + pp;
        const int b = p >> 12;
        const float qx = xyz[p * 3 + 0];
        const float qy = xyz[p * 3 + 1];
        const float qz = xyz[p * 3 + 2];
        const int2* kp = g_knn_pair + (size_t)p * KK;

        // ---- dfg layer 1: 4 k at a time, swizzled transpose store -------
        const int sA = (c0 >> 3) & 3;
#pragma unroll
        for (int kb = 0; kb < 4; kb++) {
            float2 hk[4];
#pragma unroll
            for (int kk = 0; kk < 4; kk++) {
                const int2 pr = kp[kb * 4 + kk];     // uniform broadcast LDG
                const int   j  = pr.x;
                const float dk = __int_as_float(pr.y);
                const float* nb = xyz + ((size_t)(b << 12) + j) * 3;
                const float g0 = nb[0], g1 = nb[1], g2 = nb[2];
                const float g3 = g0 - qx, g4 = g1 - qy, g5 = g2 - qz;
                float h0 = lb10, h1 = lb11;
                h0 = fmaf(g0, w1r0[0], h0); h1 = fmaf(g0, w1r1[0], h1);
                h0 = fmaf(g1, w1r0[1], h0); h1 = fmaf(g1, w1r1[1], h1);
                h0 = fmaf(g2, w1r0[2], h0); h1 = fmaf(g2, w1r1[2], h1);
                h0 = fmaf(g3, w1r0[3], h0); h1 = fmaf(g3, w1r1[3], h1);
                h0 = fmaf(g4, w1r0[4], h0); h1 = fmaf(g4, w1r1[4], h1);
                h0 = fmaf(g5, w1r0[5], h0); h1 = fmaf(g5, w1r1[5], h1);
                h0 = fmaf(dk, w1r0[6], h0); h1 = fmaf(dk, w1r1[6], h1);
                hk[kk] = make_float2(fmaxf(h0, 0.0f), fmaxf(h1, 0.0f));
            }
            const int slot = (kb ^ sA) << 2;
            *(float4*)(ws + c0 * 20 + slot) =
                make_float4(hk[0].x, hk[1].x, hk[2].x, hk[3].x);
            *(float4*)(ws + c1 * 20 + slot) =
                make_float4(hk[0].y, hk[1].y, hk[2].y, hk[3].y);
        }
        __syncwarp();

        // ---- dfg layer 2: 16-k batched, broadcast hid reads -------------
        u64 a0[8], a1[8];
        {
            u64 bb0 = f2pack(lb20, lb20), bb1 = f2pack(lb21, lb21);
#pragma unroll
            for (int m = 0; m < 8; m++) { a0[m] = bb0; a1[m] = bb1; }
        }
#pragma unroll
        for (int o = 0; o < 8; o++) {
#pragma unroll
            for (int tt = 0; tt < 8; tt++) {
                const int t = o * 8 + tt;
                const int sw = (t >> 3) & 3;
                const float2 w = *(const float2*)&sm[D_W2 + t * 64 + c0];
                const u64 w00 = f2pack(w.x, w.x);
                const u64 w11 = f2pack(w.y, w.y);
                const unsigned rowa = hidT32 + (unsigned)(t * 20) * 4u;
#pragma unroll
                for (int g = 0; g < 4; g++) {
                    u64 h01, h23;
                    lds2x64(h01, h23, rowa + (unsigned)(((g ^ sw) << 2) * 4));
                    const int m = g << 1;
                    a0[m]     = ffma2(h01, w00, a0[m]);
                    a0[m + 1] = ffma2(h23, w00, a0[m + 1]);
                    a1[m]     = ffma2(h01, w11, a1[m]);
                    a1[m + 1] = ffma2(h23, w11, a1[m + 1]);
                }
            }
        }
        __syncwarp();

        // ---- aggregation over k -----------------------------------------
        float agg0 = 0.0f, agg1 = 0.0f;
#pragma unroll
        for (int m = 0; m < 8; m++) {
            float oE0, oO0, oE1, oO1;
            f2unpack(a0[m], oE0, oO0);
            f2unpack(a1[m], oE1, oO1);
#pragma unroll
            for (int kk = 0; kk < 2; kk++) {
                const int k = 2 * m + kk;
                const float o0 = kk ? oO0 : oE0;
                const float o1 = kk ? oO1 : oE1;
                const int2 pr = kp[k];               // L1-hit broadcast
                const int   j  = pr.x;
                const float dk = __int_as_float(pr.y);
                const float* nb = xyz + ((size_t)(b << 12) + j) * 3;
                const float g0 = nb[0], g1 = nb[1], g2 = nb[2];
                const float* prow = points + ((size_t)(b << 12) + j) * CPN;
                float gp0 = (c0 >= 7) ? prow[c0 - 7] : 0.0f;
                float gp1 = (c1 >= 7) ? prow[c1 - 7] : 0.0f;
                if (lane == 0)      { gp0 = g0; gp1 = g1; }
                else if (lane == 1) { gp0 = g2; gp1 = g0 - qx; }
                else if (lane == 2) { gp0 = g1 - qy; gp1 = g2 - qz; }
                else if (lane == 3) { gp0 = dk; }
                agg0 = fmaf(o0, gp0, agg0);
                agg1 = fmaf(o1, gp1, agg1);
            }
        }
        agg0 *= 0.0625f; agg1 *= 0.0625f;

        float* hb = g_h67 + (size_t)p * 68;
        *(float2*)&hb[c0] = make_float2(agg0, agg1);
        if (lane == 0) { hb[64] = qx; hb[65] = qy; hb[66] = qz; }
        __syncwarp();
    }
}

// ============================================================================
// mlp kernel: M1/M2/SC in SMEM (82.7KB) + 8 warps x 3.2KB = 108KB
// -> 2 blocks/SM.  mlp2 + shortcut fused for ILP (8 independent chains).
// ============================================================================
#define MW    8
#define MPPW  4
#define MTPB  (MW * 32)

#define M_M1   0
#define M_MB1  8576
#define M_M2   8704
#define M_MB2  16896
#define M_SC   16960
#define M_SCB  20608
#define M_SCR  20672
#define M_WS   800
#define MSMEM_FLOATS (M_SCR + MW * M_WS)
#define MSMEM_BYTES  (MSMEM_FLOATS * 4)

__global__ __launch_bounds__(MTPB)
void mlp_kernel(const float* __restrict__ points,
                const float* __restrict__ m1, const float* __restrict__ mb1,
                const float* __restrict__ m2, const float* __restrict__ mb2,
                const float* __restrict__ sc, const float* __restrict__ scb,
                float* __restrict__ out) {
    extern __shared__ float sm[];

    for (int t = threadIdx.x; t < 8576; t += MTPB) sm[M_M1 + t]  = m1[t];
    for (int t = threadIdx.x; t < 128; t += MTPB)  sm[M_MB1 + t] = mb1[t];
    for (int t = threadIdx.x; t < 8192; t += MTPB) sm[M_M2 + t]  = m2[t];
    for (int t = threadIdx.x; t < 64;  t += MTPB)  sm[M_MB2 + t] = mb2[t];
    for (int t = threadIdx.x; t < 3648; t += MTPB) sm[M_SC + t]  = sc[t];
    for (int t = threadIdx.x; t < 64;  t += MTPB)  sm[M_SCB + t] = scb[t];
    __syncthreads();

    const int warp = threadIdx.x >> 5;
    const int lane = threadIdx.x & 31;
    const int c0 = 2 * lane;
    const int c4 = 4 * lane;

    float* h67b  = sm + M_SCR + warp * M_WS;
    float* h128b = h67b + 272;

    const unsigned smbase = (unsigned)__cvta_generic_to_shared(sm);
    const int pbase = blockIdx.x * (MW * MPPW) + warp * MPPW;

#pragma unroll
    for (int pp = 0; pp < MPPW; pp++) {
        const float* src = g_h67 + (size_t)(pbase + pp) * 68;
        for (int t = lane; t < 68; t += 32) h67b[pp * 68 + t] = src[t];
    }
    __syncwarp();

    // mlp1: [67] -> [128], relu.  input order = [xyz(3), agg(64)]
    {
        u64 acc[MPPW][2];
        const float4 bbv = *(const float4*)&sm[M_MB1 + c4];
        const u64 bb01 = f2pack(bbv.x, bbv.y), bb23 = f2pack(bbv.z, bbv.w);
#pragma unroll
        for (int pp = 0; pp < MPPW; pp++) { acc[pp][0] = bb01; acc[pp][1] = bb23; }
        const unsigned m1base = smbase + (unsigned)(M_M1 + c4) * 4u;

#pragma unroll
        for (int t = 0; t < 3; t++) {
            u64 w01, w23; lds2x64(w01, w23, m1base + (unsigned)(t * 128) * 4u);
#pragma unroll
            for (int pp = 0; pp < MPPW; pp++) {
                const float v = h67b[pp * 68 + 64 + t];
                const u64 vv = f2pack(v, v);
                acc[pp][0] = ffma2(w01, vv, acc[pp][0]);
                acc[pp][1] = ffma2(w23, vv, acc[pp][1]);
            }
        }
#pragma unroll 4
        for (int i = 0; i < 64; i++) {
            u64 w01, w23; lds2x64(w01, w23, m1base + (unsigned)((3 + i) * 128) * 4u);
#pragma unroll
            for (int pp = 0; pp < MPPW; pp++) {
                const float v = h67b[pp * 68 + i];
                const u64 vv = f2pack(v, v);
                acc[pp][0] = ffma2(w01, vv, acc[pp][0]);
                acc[pp][1] = ffma2(w23, vv, acc[pp][1]);
            }
        }
        __syncwarp();
#pragma unroll
        for (int pp = 0; pp < MPPW; pp++) {
            float x0, x1, x2, x3;
            f2unpack(acc[pp][0], x0, x1);
            f2unpack(acc[pp][1], x2, x3);
            *(float4*)&h128b[pp * 128 + c4] =
                make_float4(fmaxf(x0, 0.0f), fmaxf(x1, 0.0f),
                            fmaxf(x2, 0.0f), fmaxf(x3, 0.0f));
        }
    }
    __syncwarp();

    // reuse h67b as prow staging (mlp1 reads complete)
#pragma unroll
    for (int pp = 0; pp < MPPW; pp++) {
        const float* ps = points + (size_t)(pbase + pp) * CPN;
        for (int t = lane; t < CPN; t += 32) h67b[pp * 68 + t] = ps[t];
    }
    __syncwarp();

    // mlp2 + shortcut FUSED over t<57 (8 independent FFMA2 chains), then
    // mlp2-only tail t=57..127.  Per-accumulator order unchanged.
    u64 om[MPPW], orr[MPPW];
    {
        const u64 mb = *(const u64*)&sm[M_MB2 + c0];
        const u64 sb = *(const u64*)&sm[M_SCB + c0];
#pragma unroll
        for (int pp = 0; pp < MPPW; pp++) { om[pp] = mb; orr[pp] = sb; }

#pragma unroll 3
        for (int t = 0; t < CPN; t++) {
            const u64 wp2 = *(const u64*)&sm[M_M2 + t * 64 + c0];
            const u64 wsc = *(const u64*)&sm[M_SC + t * 64 + c0];
#pragma unroll
            for (int pp = 0; pp < MPPW; pp++) {
                const float v2 = h128b[pp * 128 + t];
                const float vs = h67b[pp * 68 + t];
                om[pp]  = ffma2(wp2, f2pack(v2, v2), om[pp]);
                orr[pp] = ffma2(wsc, f2pack(vs, vs), orr[pp]);
            }
        }
#pragma unroll 4
        for (int t = CPN; t < 128; t++) {
            const u64 wp2 = *(const u64*)&sm[M_M2 + t * 64 + c0];
#pragma unroll
            for (int pp = 0; pp < MPPW; pp++) {
                const float v2 = h128b[pp * 128 + t];
                om[pp] = ffma2(wp2, f2pack(v2, v2), om[pp]);
            }
        }
    }

#pragma unroll
    for (int pp = 0; pp < MPPW; pp++) {
        float o0, o1, r0, r1;
        f2unpack(om[pp], o0, o1);
        f2unpack(orr[pp], r0, r1);
        const int p = pbase + pp;
        *(float2*)&out[(size_t)p * 64 + c0] =
            make_float2(fmaxf(r0 + o0, 0.0f), fmaxf(r1 + o1, 0.0f));
    }
}

// ============================================================================
extern "C" void kernel_launch(void* const* d_in, const int* in_sizes, int n_in,
                              void* d_out, int out_size) {
    const float* xyz    = (const float*)d_in[0];
    const float* points = (const float*)d_in[1];
    const float* w1     = (const float*)d_in[2];
    const float* b1     = (const float*)d_in[3];
    const float* w2     = (const float*)d_in[4];
    const float* b2     = (const float*)d_in[5];
    const float* m1     = (const float*)d_in[6];
    const float* mb1    = (const float*)d_in[7];
    const float* m2     = (const float*)d_in[8];
    const float* mb2    = (const float*)d_in[9];
    const float* sc     = (const float*)d_in[10];
    const float* scb    = (const float*)d_in[11];
    float* out = (float*)d_out;
    (void)in_sizes; (void)n_in; (void)out_size;

    grid_build<<<BB, 512>>>(xyz);
    knn_query<<<dim3(NN / 128, BB), 128>>>();

    cudaFuncSetAttribute(dfg_kernel,
                         cudaFuncAttributeMaxDynamicSharedMemorySize,
                         DSMEM_BYTES);
    dfg_kernel<<<BB * NN / (DW * DPPW), DTPB, DSMEM_BYTES>>>(
        xyz, points, w1, b1, w2, b2);

    cudaFuncSetAttribute(mlp_kernel,
                         cudaFuncAttributeMaxDynamicSharedMemorySize,
                         MSMEM_BYTES);
    mlp_kernel<<<BB * NN / (MW * MPPW), MTPB, MSMEM_BYTES>>>(
        points, m1, mb1, m2, mb2, sc, scb, out);
}

// round 8
// speedup vs baseline: 1.1570x; 1.1570x over previous
#include <cuda_runtime.h>
#include <stdint.h>

#define BB   8
#define NN   4096
#define CPN  57
#define KK   16
#define THR  0.04f
#define GD   10          // cells per dim
#define NC2  1000        // GD^3
#define NBIN 64
#define TCAP 20

// ---------------- scratch (device globals; no allocation allowed) -----------
__device__ int2   g_knn_pair[BB * NN * KK];   // (idx, dist bits) interleaved
__device__ int    g_off[BB * 1024];
__device__ float4 g_sx[BB * NN];
__device__ int    g_sj[BB * NN];
__device__ float  g_h67[BB * NN * 68];        // [agg(64) | xyz(3) | pad]

// ---------------------------------------------------------------------------
// f32x2 packed helpers
// ---------------------------------------------------------------------------
typedef unsigned long long u64;
__device__ __forceinline__ u64 f2pack(float a, float b) {
    u64 r; asm("mov.b64 %0,{%1,%2};" : "=l"(r) : "f"(a), "f"(b)); return r;
}
__device__ __forceinline__ void f2unpack(u64 v, float& a, float& b) {
    asm("mov.b64 {%0,%1},%2;" : "=f"(a), "=f"(b) : "l"(v));
}
__device__ __forceinline__ u64 ffma2(u64 a, u64 b, u64 c) {
    u64 d; asm("fma.rn.f32x2 %0,%1,%2,%3;" : "=l"(d) : "l"(a), "l"(b), "l"(c));
    return d;
}
__device__ __forceinline__ void lds2x64(u64& a, u64& b, unsigned addr) {
    asm volatile("ld.shared.v2.b64 {%0,%1},[%2];"
                 : "=l"(a), "=l"(b) : "r"(addr));
}

// ---------------------------------------------------------------------------
// Fused grid build: one block per batch, 10^3 cells (cell = radius/2 = 0.1).
// ---------------------------------------------------------------------------
__device__ __forceinline__ int cell_of(float x, float y, float z) {
    int cx = min((int)(x * 10.0f), GD - 1);
    int cy = min((int)(y * 10.0f), GD - 1);
    int cz = min((int)(z * 10.0f), GD - 1);
    return (cx * GD + cy) * GD + cz;
}

__global__ void grid_build(const float* __restrict__ xyz) {
    __shared__ int scnt[NC2];
    __shared__ int soff[NC2 + 1];
    __shared__ int scur[NC2];
    const int b = blockIdx.x;
    const float* bx = xyz + (size_t)b * NN * 3;

    for (int t = threadIdx.x; t < NC2; t += 512) scnt[t] = 0;
    __syncthreads();

    for (int i = threadIdx.x; i < NN; i += 512) {
        float x = bx[i * 3 + 0], y = bx[i * 3 + 1], z = bx[i * 3 + 2];
        atomicAdd(&scnt[cell_of(x, y, z)], 1);
    }
    __syncthreads();

    if (threadIdx.x == 0) {
        int acc = 0;
        for (int c = 0; c < NC2; c++) { soff[c] = acc; scur[c] = acc; acc += scnt[c]; }
        soff[NC2] = acc;
    }
    __syncthreads();

    for (int t = threadIdx.x; t <= NC2; t += 512) g_off[b * 1024 + t] = soff[t];

    for (int i = threadIdx.x; i < NN; i += 512) {
        float x = bx[i * 3 + 0], y = bx[i * 3 + 1], z = bx[i * 3 + 2];
        int cell = cell_of(x, y, z);
        int pos = atomicAdd(&scur[cell], 1);
        float sq = fmaf(z, z, fmaf(y, y, x * x));
        g_sx[(b << 12) + pos] = make_float4(x, y, z, sq);
        g_sj[(b << 12) + pos] = i;
    }
}

// ---------------------------------------------------------------------------
// kNN query: histogram two-pass selection over a +-2-cell (0.5^3) box.
// Superset of the r=0.2 ball -> identical selected set vs coarser grid.
// ---------------------------------------------------------------------------
#define KNN_SCAN(BODY)                                                        \
    for (int dx = -2; dx <= 2; dx++) {                                        \
        int ncx = cx + dx; if (ncx < 0 || ncx > GD - 1) continue;             \
        for (int dy = -2; dy <= 2; dy++) {                                    \
            int ncy = cy + dy; if (ncy < 0 || ncy > GD - 1) continue;         \
            int cb2 = b * 1024 + (ncx * GD + ncy) * GD;                       \
            int sbeg = g_off[cb2 + czlo];                                     \
            int send = g_off[cb2 + czhi + 1];                                 \
            for (int s = sbeg; s < send; s++) {                               \
                float4 c = g_sx[(b << 12) + s];                               \
                float dot = fmaf(q.z, c.z, fmaf(q.y, c.y, q.x * c.x));        \
                float rhs = fmaf(0.5f, c.w, qoff);                            \
                if (dot >= rhs) {                                             \
                    float t1 = qsq + c.w;                                     \
                    float d = __fsub_rn(t1, __fmul_rn(2.0f, dot));            \
                    if (d <= THR) { BODY }                                    \
                }                                                             \
            }                                                                 \
        }                                                                     \
    }

__global__ __launch_bounds__(128) void knn_query() {
    __shared__ unsigned short hist[NBIN * 128];
    __shared__ int2 tl[128 * TCAP];
    const int tid = threadIdx.x;
    const int b = blockIdx.y;
    const int slot = blockIdx.x * 128 + tid;
    const float4 q = g_sx[(b << 12) + slot];
    const int qi = g_sj[(b << 12) + slot];
    const float qsq = q.w;
    const int cx = min((int)(q.x * 10.0f), GD - 1);
    const int cy = min((int)(q.y * 10.0f), GD - 1);
    const int cz = min((int)(q.z * 10.0f), GD - 1);
    const float qoff = 0.5f * (qsq - THR) - 1e-5f;
    const int czlo = max(cz - 2, 0), czhi = min(cz + 2, GD - 1);

#pragma unroll 8
    for (int bn = 0; bn < NBIN; bn++) hist[bn * 128 + tid] = 0;

    // ---- pass A: histogram of exact d -----------------------------------
    KNN_SCAN({
        int bn = max(0, min(NBIN - 1, (int)(d * 1600.0f)));   // 64 / 0.04
        hist[bn * 128 + tid]++;
    })

    // ---- threshold: smallest bin with cum >= K --------------------------
    int tstar = NBIN, cum = 0;
#pragma unroll 8
    for (int bn = 0; bn < NBIN; bn++) {
        int c = (int)hist[bn * 128 + tid];
        if (tstar == NBIN && cum + c >= KK) tstar = bn;
        cum += c;
    }

    const int base = (b * NN + qi) * KK;
    int cnt = 0, tcnt = 0;

    // ---- pass B: direct-stream + threshold list -------------------------
    KNN_SCAN({
        int bn = max(0, min(NBIN - 1, (int)(d * 1600.0f)));
        if (bn < tstar) {
            int j = g_sj[(b << 12) + s];
            g_knn_pair[base + cnt] =
                make_int2(j, __float_as_int(fmaxf(d, 0.0f)));
            cnt++;
        } else if (bn == tstar && tcnt < TCAP) {
            int j = g_sj[(b << 12) + s];
            tl[tid * TCAP + tcnt] = make_int2(j, __float_as_int(d));
            tcnt++;
        }
    })

    // ---- resolve threshold bin by exact (d, j) lexicographic order ------
    if (tstar < NBIN) {
        int need = KK - cnt;
        if (need > tcnt) need = tcnt;
        for (int s2 = 0; s2 < need; s2++) {
            float bd = 3.0e38f; int bj = 0x7fffffff, bi = -1;
            for (int i2 = 0; i2 < tcnt; i2++) {
                int2 e = tl[tid * TCAP + i2];
                float dv = __int_as_float(e.y);
                bool g = (dv < bd) || (dv == bd && e.x < bj);
                if (g) { bd = dv; bj = e.x; bi = i2; }
            }
            tl[tid * TCAP + bi].y = __float_as_int(3.0e38f);
            g_knn_pair[base + cnt] =
                make_int2(bj, __float_as_int(fmaxf(bd, 0.0f)));
            cnt++;
        }
    }
    for (; cnt < KK; cnt++) g_knn_pair[base + cnt] = make_int2(qi, 0);
}

// ============================================================================
// dfg kernel: W1/W2 in SMEM (18.7KB) + 8 warps x 5.2KB hidT = 60KB
// (exact R6 configuration — no launch_bounds min-blocks).
// ============================================================================
#define DW    8
#define DPPW  8
#define DTPB  (DW * 32)

#define D_W1  0
#define D_B1  448
#define D_W2  512
#define D_B2  4608
#define D_SCR 4672
#define D_WS  1296
#define DSMEM_FLOATS (D_SCR + DW * D_WS)
#define DSMEM_BYTES  (DSMEM_FLOATS * 4)

__global__ __launch_bounds__(DTPB)
void dfg_kernel(const float* __restrict__ xyz,
                const float* __restrict__ points,
                const float* __restrict__ w1, const float* __restrict__ b1,
                const float* __restrict__ w2, const float* __restrict__ b2) {
    extern __shared__ float sm[];

    for (int t = threadIdx.x; t < 448; t += DTPB)  sm[D_W1 + t] = w1[t];
    for (int t = threadIdx.x; t < 64;  t += DTPB)  sm[D_B1 + t] = b1[t];
    for (int t = threadIdx.x; t < 4096; t += DTPB) sm[D_W2 + t] = w2[t];
    for (int t = threadIdx.x; t < 64;  t += DTPB)  sm[D_B2 + t] = b2[t];
    __syncthreads();

    const int warp = threadIdx.x >> 5;
    const int lane = threadIdx.x & 31;
    const int c0 = 2 * lane, c1 = c0 + 1;

    float w1r0[7], w1r1[7];
#pragma unroll
    for (int t = 0; t < 7; t++) {
        w1r0[t] = sm[D_W1 + t * 64 + c0];
        w1r1[t] = sm[D_W1 + t * 64 + c1];
    }
    const float lb10 = sm[D_B1 + c0], lb11 = sm[D_B1 + c1];
    const float lb20 = sm[D_B2 + c0], lb21 = sm[D_B2 + c1];

    float* ws = sm + D_SCR + warp * D_WS;
    const unsigned hidT32 =
        (unsigned)__cvta_generic_to_shared(sm) +
        (unsigned)(D_SCR + warp * D_WS) * 4u;

#pragma unroll 1
    for (int pp = 0; pp < DPPW; pp++) {
        const int p = blockIdx.x * (DW * DPPW) + warp * DPPW + pp;
        const int b = p >> 12;
        const float qx = xyz[p * 3 + 0];
        const float qy = xyz[p * 3 + 1];
        const float qz = xyz[p * 3 + 2];
        const int2* kp = g_knn_pair + (size_t)p * KK;

        // ---- dfg layer 1: 4 k at a time, swizzled transpose store -------
        const int sA = (c0 >> 3) & 3;
#pragma unroll
        for (int kb = 0; kb < 4; kb++) {
            float2 hk[4];
#pragma unroll
            for (int kk = 0; kk < 4; kk++) {
                const int2 pr = kp[kb * 4 + kk];     // uniform broadcast LDG
                const int   j  = pr.x;
                const float dk = __int_as_float(pr.y);
                const float* nb = xyz + ((size_t)(b << 12) + j) * 3;
                const float g0 = nb[0], g1 = nb[1], g2 = nb[2];
                const float g3 = g0 - qx, g4 = g1 - qy, g5 = g2 - qz;
                float h0 = lb10, h1 = lb11;
                h0 = fmaf(g0, w1r0[0], h0); h1 = fmaf(g0, w1r1[0], h1);
                h0 = fmaf(g1, w1r0[1], h0); h1 = fmaf(g1, w1r1[1], h1);
                h0 = fmaf(g2, w1r0[2], h0); h1 = fmaf(g2, w1r1[2], h1);
                h0 = fmaf(g3, w1r0[3], h0); h1 = fmaf(g3, w1r1[3], h1);
                h0 = fmaf(g4, w1r0[4], h0); h1 = fmaf(g4, w1r1[4], h1);
                h0 = fmaf(g5, w1r0[5], h0); h1 = fmaf(g5, w1r1[5], h1);
                h0 = fmaf(dk, w1r0[6], h0); h1 = fmaf(dk, w1r1[6], h1);
                hk[kk] = make_float2(fmaxf(h0, 0.0f), fmaxf(h1, 0.0f));
            }
            const int slot = (kb ^ sA) << 2;
            *(float4*)(ws + c0 * 20 + slot) =
                make_float4(hk[0].x, hk[1].x, hk[2].x, hk[3].x);
            *(float4*)(ws + c1 * 20 + slot) =
                make_float4(hk[0].y, hk[1].y, hk[2].y, hk[3].y);
        }
        __syncwarp();

        // ---- dfg layer 2: 16-k batched, broadcast hid reads -------------
        u64 a0[8], a1[8];
        {
            u64 bb0 = f2pack(lb20, lb20), bb1 = f2pack(lb21, lb21);
#pragma unroll
            for (int m = 0; m < 8; m++) { a0[m] = bb0; a1[m] = bb1; }
        }
#pragma unroll
        for (int o = 0; o < 8; o++) {
#pragma unroll
            for (int tt = 0; tt < 8; tt++) {
                const int t = o * 8 + tt;
                const int sw = (t >> 3) & 3;
                const float2 w = *(const float2*)&sm[D_W2 + t * 64 + c0];
                const u64 w00 = f2pack(w.x, w.x);
                const u64 w11 = f2pack(w.y, w.y);
                const unsigned rowa = hidT32 + (unsigned)(t * 20) * 4u;
#pragma unroll
                for (int g = 0; g < 4; g++) {
                    u64 h01, h23;
                    lds2x64(h01, h23, rowa + (unsigned)(((g ^ sw) << 2) * 4));
                    const int m = g << 1;
                    a0[m]     = ffma2(h01, w00, a0[m]);
                    a0[m + 1] = ffma2(h23, w00, a0[m + 1]);
                    a1[m]     = ffma2(h01, w11, a1[m]);
                    a1[m + 1] = ffma2(h23, w11, a1[m + 1]);
                }
            }
        }
        __syncwarp();

        // ---- aggregation over k -----------------------------------------
        float agg0 = 0.0f, agg1 = 0.0f;
#pragma unroll
        for (int m = 0; m < 8; m++) {
            float oE0, oO0, oE1, oO1;
            f2unpack(a0[m], oE0, oO0);
            f2unpack(a1[m], oE1, oO1);
#pragma unroll
            for (int kk = 0; kk < 2; kk++) {
                const int k = 2 * m + kk;
                const float o0 = kk ? oO0 : oE0;
                const float o1 = kk ? oO1 : oE1;
                const int2 pr = kp[k];               // L1-hit broadcast
                const int   j  = pr.x;
                const float dk = __int_as_float(pr.y);
                const float* nb = xyz + ((size_t)(b << 12) + j) * 3;
                const float g0 = nb[0], g1 = nb[1], g2 = nb[2];
                const float* prow = points + ((size_t)(b << 12) + j) * CPN;
                float gp0 = (c0 >= 7) ? prow[c0 - 7] : 0.0f;
                float gp1 = (c1 >= 7) ? prow[c1 - 7] : 0.0f;
                if (lane == 0)      { gp0 = g0; gp1 = g1; }
                else if (lane == 1) { gp0 = g2; gp1 = g0 - qx; }
                else if (lane == 2) { gp0 = g1 - qy; gp1 = g2 - qz; }
                else if (lane == 3) { gp0 = dk; }
                agg0 = fmaf(o0, gp0, agg0);
                agg1 = fmaf(o1, gp1, agg1);
            }
        }
        agg0 *= 0.0625f; agg1 *= 0.0625f;

        float* hb = g_h67 + (size_t)p * 68;
        *(float2*)&hb[c0] = make_float2(agg0, agg1);
        if (lane == 0) { hb[64] = qx; hb[65] = qy; hb[66] = qz; }
        __syncwarp();
    }
}

// ============================================================================
// mlp kernel: exact R6 configuration (separate mlp2 and shortcut loops).
// ============================================================================
#define MW    8
#define MPPW  4
#define MTPB  (MW * 32)

#define M_M1   0
#define M_MB1  8576
#define M_M2   8704
#define M_MB2  16896
#define M_SC   16960
#define M_SCB  20608
#define M_SCR  20672
#define M_WS   800
#define MSMEM_FLOATS (M_SCR + MW * M_WS)
#define MSMEM_BYTES  (MSMEM_FLOATS * 4)

__global__ __launch_bounds__(MTPB)
void mlp_kernel(const float* __restrict__ points,
                const float* __restrict__ m1, const float* __restrict__ mb1,
                const float* __restrict__ m2, const float* __restrict__ mb2,
                const float* __restrict__ sc, const float* __restrict__ scb,
                float* __restrict__ out) {
    extern __shared__ float sm[];

    for (int t = threadIdx.x; t < 8576; t += MTPB) sm[M_M1 + t]  = m1[t];
    for (int t = threadIdx.x; t < 128; t += MTPB)  sm[M_MB1 + t] = mb1[t];
    for (int t = threadIdx.x; t < 8192; t += MTPB) sm[M_M2 + t]  = m2[t];
    for (int t = threadIdx.x; t < 64;  t += MTPB)  sm[M_MB2 + t] = mb2[t];
    for (int t = threadIdx.x; t < 3648; t += MTPB) sm[M_SC + t]  = sc[t];
    for (int t = threadIdx.x; t < 64;  t += MTPB)  sm[M_SCB + t] = scb[t];
    __syncthreads();

    const int warp = threadIdx.x >> 5;
    const int lane = threadIdx.x & 31;
    const int c0 = 2 * lane;
    const int c4 = 4 * lane;

    float* h67b  = sm + M_SCR + warp * M_WS;
    float* h128b = h67b + 272;

    const unsigned smbase = (unsigned)__cvta_generic_to_shared(sm);
    const int pbase = blockIdx.x * (MW * MPPW) + warp * MPPW;

#pragma unroll
    for (int pp = 0; pp < MPPW; pp++) {
        const float* src = g_h67 + (size_t)(pbase + pp) * 68;
        for (int t = lane; t < 68; t += 32) h67b[pp * 68 + t] = src[t];
    }
    __syncwarp();

    // mlp1: [67] -> [128], relu.  input order = [xyz(3), agg(64)]
    {
        u64 acc[MPPW][2];
        const float4 bbv = *(const float4*)&sm[M_MB1 + c4];
        const u64 bb01 = f2pack(bbv.x, bbv.y), bb23 = f2pack(bbv.z, bbv.w);
#pragma unroll
        for (int pp = 0; pp < MPPW; pp++) { acc[pp][0] = bb01; acc[pp][1] = bb23; }
        const unsigned m1base = smbase + (unsigned)(M_M1 + c4) * 4u;

#pragma unroll
        for (int t = 0; t < 3; t++) {
            u64 w01, w23; lds2x64(w01, w23, m1base + (unsigned)(t * 128) * 4u);
#pragma unroll
            for (int pp = 0; pp < MPPW; pp++) {
                const float v = h67b[pp * 68 + 64 + t];
                const u64 vv = f2pack(v, v);
                acc[pp][0] = ffma2(w01, vv, acc[pp][0]);
                acc[pp][1] = ffma2(w23, vv, acc[pp][1]);
            }
        }
#pragma unroll 4
        for (int i = 0; i < 64; i++) {
            u64 w01, w23; lds2x64(w01, w23, m1base + (unsigned)((3 + i) * 128) * 4u);
#pragma unroll
            for (int pp = 0; pp < MPPW; pp++) {
                const float v = h67b[pp * 68 + i];
                const u64 vv = f2pack(v, v);
                acc[pp][0] = ffma2(w01, vv, acc[pp][0]);
                acc[pp][1] = ffma2(w23, vv, acc[pp][1]);
            }
        }
        __syncwarp();
#pragma unroll
        for (int pp = 0; pp < MPPW; pp++) {
            float x0, x1, x2, x3;
            f2unpack(acc[pp][0], x0, x1);
            f2unpack(acc[pp][1], x2, x3);
            *(float4*)&h128b[pp * 128 + c4] =
                make_float4(fmaxf(x0, 0.0f), fmaxf(x1, 0.0f),
                            fmaxf(x2, 0.0f), fmaxf(x3, 0.0f));
        }
    }
    __syncwarp();

#pragma unroll
    for (int pp = 0; pp < MPPW; pp++) {
        const float* ps = points + (size_t)(pbase + pp) * CPN;
        for (int t = lane; t < CPN; t += 32) h67b[pp * 68 + t] = ps[t];
    }
    __syncwarp();

    // mlp2: [128] -> [64]
    u64 om[MPPW];
    {
        const u64 mb = *(const u64*)&sm[M_MB2 + c0];
#pragma unroll
        for (int pp = 0; pp < MPPW; pp++) om[pp] = mb;
#pragma unroll 4
        for (int t = 0; t < 128; t++) {
            const u64 wp = *(const u64*)&sm[M_M2 + t * 64 + c0];
#pragma unroll
            for (int pp = 0; pp < MPPW; pp++) {
                const float v = h128b[pp * 128 + t];
                om[pp] = ffma2(wp, f2pack(v, v), om[pp]);
            }
        }
    }

    // shortcut: points @ sc_w + sc_b
    u64 orr[MPPW];
    {
        const u64 sb = *(const u64*)&sm[M_SCB + c0];
#pragma unroll
        for (int pp = 0; pp < MPPW; pp++) orr[pp] = sb;
#pragma unroll 4
        for (int t = 0; t < CPN; t++) {
            const u64 wp = *(const u64*)&sm[M_SC + t * 64 + c0];
#pragma unroll
            for (int pp = 0; pp < MPPW; pp++) {
                const float v = h67b[pp * 68 + t];
                orr[pp] = ffma2(wp, f2pack(v, v), orr[pp]);
            }
        }
    }

#pragma unroll
    for (int pp = 0; pp < MPPW; pp++) {
        float o0, o1, r0, r1;
        f2unpack(om[pp], o0, o1);
        f2unpack(orr[pp], r0, r1);
        const int p = pbase + pp;
        *(float2*)&out[(size_t)p * 64 + c0] =
            make_float2(fmaxf(r0 + o0, 0.0f), fmaxf(r1 + o1, 0.0f));
    }
}

// ============================================================================
extern "C" void kernel_launch(void* const* d_in, const int* in_sizes, int n_in,
                              void* d_out, int out_size) {
    const float* xyz    = (const float*)d_in[0];
    const float* points = (const float*)d_in[1];
    const float* w1     = (const float*)d_in[2];
    const float* b1     = (const float*)d_in[3];
    const float* w2     = (const float*)d_in[4];
    const float* b2     = (const float*)d_in[5];
    const float* m1     = (const float*)d_in[6];
    const float* mb1    = (const float*)d_in[7];
    const float* m2     = (const float*)d_in[8];
    const float* mb2    = (const float*)d_in[9];
    const float* sc     = (const float*)d_in[10];
    const float* scb    = (const float*)d_in[11];
    float* out = (float*)d_out;
    (void)in_sizes; (void)n_in; (void)out_size;

    grid_build<<<BB, 512>>>(xyz);
    knn_query<<<dim3(NN / 128, BB), 128>>>();

    cudaFuncSetAttribute(dfg_kernel,
                         cudaFuncAttributeMaxDynamicSharedMemorySize,
                         DSMEM_BYTES);
    dfg_kernel<<<BB * NN / (DW * DPPW), DTPB, DSMEM_BYTES>>>(
        xyz, points, w1, b1, w2, b2);

    cudaFuncSetAttribute(mlp_kernel,
                         cudaFuncAttributeMaxDynamicSharedMemorySize,
                         MSMEM_BYTES);
    mlp_kernel<<<BB * NN / (MW * MPPW), MTPB, MSMEM_BYTES>>>(
        points, m1, mb1, m2, mb2, sc, scb, out);
}

// round 9
// speedup vs baseline: 1.2148x; 1.0500x over previous
#include <cuda_runtime.h>
#include <stdint.h>

#define BB   8
#define NN   4096
#define CPN  57
#define KK   16
#define THR  0.04f
#define GD   10          // cells per dim
#define NC2  1000        // GD^3
#define NBIN 64
#define TCAP 20

// ---------------- scratch (device globals; no allocation allowed) -----------
__device__ int2   g_knn_pair[BB * NN * KK];   // (idx, dist bits) interleaved
__device__ int    g_off[BB * 1024];
__device__ float4 g_sx[BB * NN];
__device__ int    g_sj[BB * NN];
__device__ float  g_h67[BB * NN * 68];        // [agg(64) | xyz(3) | pad]

// ---------------------------------------------------------------------------
// f32x2 packed helpers
// ---------------------------------------------------------------------------
typedef unsigned long long u64;
__device__ __forceinline__ u64 f2pack(float a, float b) {
    u64 r; asm("mov.b64 %0,{%1,%2};" : "=l"(r) : "f"(a), "f"(b)); return r;
}
__device__ __forceinline__ void f2unpack(u64 v, float& a, float& b) {
    asm("mov.b64 {%0,%1},%2;" : "=f"(a), "=f"(b) : "l"(v));
}
__device__ __forceinline__ u64 ffma2(u64 a, u64 b, u64 c) {
    u64 d; asm("fma.rn.f32x2 %0,%1,%2,%3;" : "=l"(d) : "l"(a), "l"(b), "l"(c));
    return d;
}
__device__ __forceinline__ void lds2x64(u64& a, u64& b, unsigned addr) {
    asm volatile("ld.shared.v2.b64 {%0,%1},[%2];"
                 : "=l"(a), "=l"(b) : "r"(addr));
}

// ---------------------------------------------------------------------------
// Fused grid build: one block per batch, 10^3 cells (cell = radius/2 = 0.1).
// ---------------------------------------------------------------------------
__device__ __forceinline__ int cell_of(float x, float y, float z) {
    int cx = min((int)(x * 10.0f), GD - 1);
    int cy = min((int)(y * 10.0f), GD - 1);
    int cz = min((int)(z * 10.0f), GD - 1);
    return (cx * GD + cy) * GD + cz;
}

__global__ void grid_build(const float* __restrict__ xyz) {
    __shared__ int scnt[NC2];
    __shared__ int soff[NC2 + 1];
    __shared__ int scur[NC2];
    const int b = blockIdx.x;
    const float* bx = xyz + (size_t)b * NN * 3;

    for (int t = threadIdx.x; t < NC2; t += 512) scnt[t] = 0;
    __syncthreads();

    for (int i = threadIdx.x; i < NN; i += 512) {
        float x = bx[i * 3 + 0], y = bx[i * 3 + 1], z = bx[i * 3 + 2];
        atomicAdd(&scnt[cell_of(x, y, z)], 1);
    }
    __syncthreads();

    if (threadIdx.x == 0) {
        int acc = 0;
        for (int c = 0; c < NC2; c++) { soff[c] = acc; scur[c] = acc; acc += scnt[c]; }
        soff[NC2] = acc;
    }
    __syncthreads();

    for (int t = threadIdx.x; t <= NC2; t += 512) g_off[b * 1024 + t] = soff[t];

    for (int i = threadIdx.x; i < NN; i += 512) {
        float x = bx[i * 3 + 0], y = bx[i * 3 + 1], z = bx[i * 3 + 2];
        int cell = cell_of(x, y, z);
        int pos = atomicAdd(&scur[cell], 1);
        float sq = fmaf(z, z, fmaf(y, y, x * x));
        g_sx[(b << 12) + pos] = make_float4(x, y, z, sq);
        g_sj[(b << 12) + pos] = i;
    }
}

// ---------------------------------------------------------------------------
// kNN query: histogram two-pass selection over a +-2-cell (0.5^3) box.
// ---------------------------------------------------------------------------
#define KNN_SCAN(BODY)                                                        \
    for (int dx = -2; dx <= 2; dx++) {                                        \
        int ncx = cx + dx; if (ncx < 0 || ncx > GD - 1) continue;             \
        for (int dy = -2; dy <= 2; dy++) {                                    \
            int ncy = cy + dy; if (ncy < 0 || ncy > GD - 1) continue;         \
            int cb2 = b * 1024 + (ncx * GD + ncy) * GD;                       \
            int sbeg = g_off[cb2 + czlo];                                     \
            int send = g_off[cb2 + czhi + 1];                                 \
            for (int s = sbeg; s < send; s++) {                               \
                float4 c = g_sx[(b << 12) + s];                               \
                float dot = fmaf(q.z, c.z, fmaf(q.y, c.y, q.x * c.x));        \
                float rhs = fmaf(0.5f, c.w, qoff);                            \
                if (dot >= rhs) {                                             \
                    float t1 = qsq + c.w;                                     \
                    float d = __fsub_rn(t1, __fmul_rn(2.0f, dot));            \
                    if (d <= THR) { BODY }                                    \
                }                                                             \
            }                                                                 \
        }                                                                     \
    }

__global__ __launch_bounds__(128) void knn_query() {
    __shared__ unsigned short hist[NBIN * 128];
    __shared__ int2 tl[128 * TCAP];
    const int tid = threadIdx.x;
    const int b = blockIdx.y;
    const int slot = blockIdx.x * 128 + tid;
    const float4 q = g_sx[(b << 12) + slot];
    const int qi = g_sj[(b << 12) + slot];
    const float qsq = q.w;
    const int cx = min((int)(q.x * 10.0f), GD - 1);
    const int cy = min((int)(q.y * 10.0f), GD - 1);
    const int cz = min((int)(q.z * 10.0f), GD - 1);
    const float qoff = 0.5f * (qsq - THR) - 1e-5f;
    const int czlo = max(cz - 2, 0), czhi = min(cz + 2, GD - 1);

#pragma unroll 8
    for (int bn = 0; bn < NBIN; bn++) hist[bn * 128 + tid] = 0;

    // ---- pass A: histogram of exact d -----------------------------------
    KNN_SCAN({
        int bn = max(0, min(NBIN - 1, (int)(d * 1600.0f)));   // 64 / 0.04
        hist[bn * 128 + tid]++;
    })

    // ---- threshold: smallest bin with cum >= K --------------------------
    int tstar = NBIN, cum = 0;
#pragma unroll 8
    for (int bn = 0; bn < NBIN; bn++) {
        int c = (int)hist[bn * 128 + tid];
        if (tstar == NBIN && cum + c >= KK) tstar = bn;
        cum += c;
    }

    const int base = (b * NN + qi) * KK;
    int cnt = 0, tcnt = 0;

    // ---- pass B: direct-stream + threshold list -------------------------
    KNN_SCAN({
        int bn = max(0, min(NBIN - 1, (int)(d * 1600.0f)));
        if (bn < tstar) {
            int j = g_sj[(b << 12) + s];
            g_knn_pair[base + cnt] =
                make_int2(j, __float_as_int(fmaxf(d, 0.0f)));
            cnt++;
        } else if (bn == tstar && tcnt < TCAP) {
            int j = g_sj[(b << 12) + s];
            tl[tid * TCAP + tcnt] = make_int2(j, __float_as_int(d));
            tcnt++;
        }
    })

    // ---- resolve threshold bin by exact (d, j) lexicographic order ------
    if (tstar < NBIN) {
        int need = KK - cnt;
        if (need > tcnt) need = tcnt;
        for (int s2 = 0; s2 < need; s2++) {
            float bd = 3.0e38f; int bj = 0x7fffffff, bi = -1;
            for (int i2 = 0; i2 < tcnt; i2++) {
                int2 e = tl[tid * TCAP + i2];
                float dv = __int_as_float(e.y);
                bool g = (dv < bd) || (dv == bd && e.x < bj);
                if (g) { bd = dv; bj = e.x; bi = i2; }
            }
            tl[tid * TCAP + bi].y = __float_as_int(3.0e38f);
            g_knn_pair[base + cnt] =
                make_int2(bj, __float_as_int(fmaxf(bd, 0.0f)));
            cnt++;
        }
    }
    for (; cnt < KK; cnt++) g_knn_pair[base + cnt] = make_int2(qi, 0);
}

// ============================================================================
// dfg kernel: 128-thread blocks (4 warps).  SMEM = 18.7KB weights +
// 4 x 5.2KB scratch = 39.4KB -> 5 blocks/SM = 20 warps (vs 16 before).
// __launch_bounds__(128,5) gives a 102-reg budget (no hard squeeze).
// ============================================================================
#define DW    4
#define DPPW  8
#define DTPB  (DW * 32)

#define D_W1  0
#define D_B1  448
#define D_W2  512
#define D_B2  4608
#define D_SCR 4672
#define D_WS  1296
#define DSMEM_FLOATS (D_SCR + DW * D_WS)
#define DSMEM_BYTES  (DSMEM_FLOATS * 4)

__global__ __launch_bounds__(DTPB, 5)
void dfg_kernel(const float* __restrict__ xyz,
                const float* __restrict__ points,
                const float* __restrict__ w1, const float* __restrict__ b1,
                const float* __restrict__ w2, const float* __restrict__ b2) {
    extern __shared__ float sm[];

    for (int t = threadIdx.x; t < 448; t += DTPB)  sm[D_W1 + t] = w1[t];
    for (int t = threadIdx.x; t < 64;  t += DTPB)  sm[D_B1 + t] = b1[t];
    for (int t = threadIdx.x; t < 4096; t += DTPB) sm[D_W2 + t] = w2[t];
    for (int t = threadIdx.x; t < 64;  t += DTPB)  sm[D_B2 + t] = b2[t];
    __syncthreads();

    const int warp = threadIdx.x >> 5;
    const int lane = threadIdx.x & 31;
    const int c0 = 2 * lane, c1 = c0 + 1;

    float w1r0[7], w1r1[7];
#pragma unroll
    for (int t = 0; t < 7; t++) {
        w1r0[t] = sm[D_W1 + t * 64 + c0];
        w1r1[t] = sm[D_W1 + t * 64 + c1];
    }
    const float lb10 = sm[D_B1 + c0], lb11 = sm[D_B1 + c1];
    const float lb20 = sm[D_B2 + c0], lb21 = sm[D_B2 + c1];

    float* ws = sm + D_SCR + warp * D_WS;
    const unsigned hidT32 =
        (unsigned)__cvta_generic_to_shared(sm) +
        (unsigned)(D_SCR + warp * D_WS) * 4u;

#pragma unroll 1
    for (int pp = 0; pp < DPPW; pp++) {
        const int p = blockIdx.x * (DW * DPPW) + warp * DPPW + pp;
        const int b = p >> 12;
        const float qx = xyz[p * 3 + 0];
        const float qy = xyz[p * 3 + 1];
        const float qz = xyz[p * 3 + 2];
        const int2* kp = g_knn_pair + (size_t)p * KK;

        // ---- dfg layer 1: 4 k at a time, swizzled transpose store -------
        const int sA = (c0 >> 3) & 3;
#pragma unroll
        for (int kb = 0; kb < 4; kb++) {
            float2 hk[4];
#pragma unroll
            for (int kk = 0; kk < 4; kk++) {
                const int2 pr = kp[kb * 4 + kk];     // uniform broadcast LDG
                const int   j  = pr.x;
                const float dk = __int_as_float(pr.y);
                const float* nb = xyz + ((size_t)(b << 12) + j) * 3;
                const float g0 = nb[0], g1 = nb[1], g2 = nb[2];
                const float g3 = g0 - qx, g4 = g1 - qy, g5 = g2 - qz;
                float h0 = lb10, h1 = lb11;
                h0 = fmaf(g0, w1r0[0], h0); h1 = fmaf(g0, w1r1[0], h1);
                h0 = fmaf(g1, w1r0[1], h0); h1 = fmaf(g1, w1r1[1], h1);
                h0 = fmaf(g2, w1r0[2], h0); h1 = fmaf(g2, w1r1[2], h1);
                h0 = fmaf(g3, w1r0[3], h0); h1 = fmaf(g3, w1r1[3], h1);
                h0 = fmaf(g4, w1r0[4], h0); h1 = fmaf(g4, w1r1[4], h1);
                h0 = fmaf(g5, w1r0[5], h0); h1 = fmaf(g5, w1r1[5], h1);
                h0 = fmaf(dk, w1r0[6], h0); h1 = fmaf(dk, w1r1[6], h1);
                hk[kk] = make_float2(fmaxf(h0, 0.0f), fmaxf(h1, 0.0f));
            }
            const int slot = (kb ^ sA) << 2;
            *(float4*)(ws + c0 * 20 + slot) =
                make_float4(hk[0].x, hk[1].x, hk[2].x, hk[3].x);
            *(float4*)(ws + c1 * 20 + slot) =
                make_float4(hk[0].y, hk[1].y, hk[2].y, hk[3].y);
        }
        __syncwarp();

        // ---- dfg layer 2: 16-k batched, broadcast hid reads -------------
        u64 a0[8], a1[8];
        {
            u64 bb0 = f2pack(lb20, lb20), bb1 = f2pack(lb21, lb21);
#pragma unroll
            for (int m = 0; m < 8; m++) { a0[m] = bb0; a1[m] = bb1; }
        }
#pragma unroll
        for (int o = 0; o < 8; o++) {
#pragma unroll
            for (int tt = 0; tt < 8; tt++) {
                const int t = o * 8 + tt;
                const int sw = (t >> 3) & 3;
                const float2 w = *(const float2*)&sm[D_W2 + t * 64 + c0];
                const u64 w00 = f2pack(w.x, w.x);
                const u64 w11 = f2pack(w.y, w.y);
                const unsigned rowa = hidT32 + (unsigned)(t * 20) * 4u;
#pragma unroll
                for (int g = 0; g < 4; g++) {
                    u64 h01, h23;
                    lds2x64(h01, h23, rowa + (unsigned)(((g ^ sw) << 2) * 4));
                    const int m = g << 1;
                    a0[m]     = ffma2(h01, w00, a0[m]);
                    a0[m + 1] = ffma2(h23, w00, a0[m + 1]);
                    a1[m]     = ffma2(h01, w11, a1[m]);
                    a1[m + 1] = ffma2(h23, w11, a1[m + 1]);
                }
            }
        }
        __syncwarp();

        // ---- aggregation over k -----------------------------------------
        float agg0 = 0.0f, agg1 = 0.0f;
#pragma unroll
        for (int m = 0; m < 8; m++) {
            float oE0, oO0, oE1, oO1;
            f2unpack(a0[m], oE0, oO0);
            f2unpack(a1[m], oE1, oO1);
#pragma unroll
            for (int kk = 0; kk < 2; kk++) {
                const int k = 2 * m + kk;
                const float o0 = kk ? oO0 : oE0;
                const float o1 = kk ? oO1 : oE1;
                const int2 pr = kp[k];               // L1-hit broadcast
                const int   j  = pr.x;
                const float dk = __int_as_float(pr.y);
                const float* nb = xyz + ((size_t)(b << 12) + j) * 3;
                const float g0 = nb[0], g1 = nb[1], g2 = nb[2];
                const float* prow = points + ((size_t)(b << 12) + j) * CPN;
                float gp0 = (c0 >= 7) ? prow[c0 - 7] : 0.0f;
                float gp1 = (c1 >= 7) ? prow[c1 - 7] : 0.0f;
                if (lane == 0)      { gp0 = g0; gp1 = g1; }
                else if (lane == 1) { gp0 = g2; gp1 = g0 - qx; }
                else if (lane == 2) { gp0 = g1 - qy; gp1 = g2 - qz; }
                else if (lane == 3) { gp0 = dk; }
                agg0 = fmaf(o0, gp0, agg0);
                agg1 = fmaf(o1, gp1, agg1);
            }
        }
        agg0 *= 0.0625f; agg1 *= 0.0625f;

        float* hb = g_h67 + (size_t)p * 68;
        *(float2*)&hb[c0] = make_float2(agg0, agg1);
        if (lane == 0) { hb[64] = qx; hb[65] = qy; hb[66] = qz; }
        __syncwarp();
    }
}

// ============================================================================
// mlp kernel: weights via L1 (__ldg), SMEM = per-warp scratch only (25.6KB)
// -> 4 blocks/SM = 32 warps (2x).  mlp2/sc use plain FFMA (no pack MOVs).
// Per-accumulator summation order identical to previous rounds.
// ============================================================================
#define MW    8
#define MPPW  4
#define MTPB  (MW * 32)
#define M_WS   800
#define MSMEM_FLOATS (MW * M_WS)
#define MSMEM_BYTES  (MSMEM_FLOATS * 4)

__global__ __launch_bounds__(MTPB)
void mlp_kernel(const float* __restrict__ points,
                const float* __restrict__ m1, const float* __restrict__ mb1,
                const float* __restrict__ m2, const float* __restrict__ mb2,
                const float* __restrict__ sc, const float* __restrict__ scb,
                float* __restrict__ out) {
    extern __shared__ float sm[];

    const int warp = threadIdx.x >> 5;
    const int lane = threadIdx.x & 31;
    const int c0 = 2 * lane;
    const int c4 = 4 * lane;

    float* h67b  = sm + warp * M_WS;   // 4 x 68, later reused as prow
    float* h128b = h67b + 272;         // 4 x 128

    const int pbase = blockIdx.x * (MW * MPPW) + warp * MPPW;

#pragma unroll
    for (int pp = 0; pp < MPPW; pp++) {
        const float* src = g_h67 + (size_t)(pbase + pp) * 68;
        for (int t = lane; t < 68; t += 32) h67b[pp * 68 + t] = src[t];
    }
    __syncwarp();

    // mlp1: [67] -> [128], relu.  input order = [xyz(3), agg(64)]
    {
        float a0[MPPW], a1[MPPW], a2[MPPW], a3[MPPW];
        const float4 bbv = __ldg((const float4*)(mb1 + c4));
#pragma unroll
        for (int pp = 0; pp < MPPW; pp++) {
            a0[pp] = bbv.x; a1[pp] = bbv.y; a2[pp] = bbv.z; a3[pp] = bbv.w;
        }

#pragma unroll
        for (int t = 0; t < 3; t++) {          // xyz rows
            const float4 w = __ldg((const float4*)(m1 + t * 128 + c4));
#pragma unroll
            for (int pp = 0; pp < MPPW; pp++) {
                const float v = h67b[pp * 68 + 64 + t];
                a0[pp] = fmaf(v, w.x, a0[pp]);
                a1[pp] = fmaf(v, w.y, a1[pp]);
                a2[pp] = fmaf(v, w.z, a2[pp]);
                a3[pp] = fmaf(v, w.w, a3[pp]);
            }
        }
#pragma unroll 4
        for (int i = 0; i < 64; i++) {         // agg rows
            const float4 w = __ldg((const float4*)(m1 + (3 + i) * 128 + c4));
#pragma unroll
            for (int pp = 0; pp < MPPW; pp++) {
                const float v = h67b[pp * 68 + i];
                a0[pp] = fmaf(v, w.x, a0[pp]);
                a1[pp] = fmaf(v, w.y, a1[pp]);
                a2[pp] = fmaf(v, w.z, a2[pp]);
                a3[pp] = fmaf(v, w.w, a3[pp]);
            }
        }
        __syncwarp();
#pragma unroll
        for (int pp = 0; pp < MPPW; pp++) {
            *(float4*)&h128b[pp * 128 + c4] =
                make_float4(fmaxf(a0[pp], 0.0f), fmaxf(a1[pp], 0.0f),
                            fmaxf(a2[pp], 0.0f), fmaxf(a3[pp], 0.0f));
        }
    }
    __syncwarp();

    // reuse h67b as prow staging (mlp1 reads complete)
#pragma unroll
    for (int pp = 0; pp < MPPW; pp++) {
        const float* ps = points + (size_t)(pbase + pp) * CPN;
        for (int t = lane; t < CPN; t += 32) h67b[pp * 68 + t] = ps[t];
    }
    __syncwarp();

    // mlp2: [128] -> [64]
    float om0[MPPW], om1[MPPW];
    {
        const float2 mb = __ldg((const float2*)(mb2 + c0));
#pragma unroll
        for (int pp = 0; pp < MPPW; pp++) { om0[pp] = mb.x; om1[pp] = mb.y; }
#pragma unroll 4
        for (int t = 0; t < 128; t++) {
            const float2 w = __ldg((const float2*)(m2 + t * 64 + c0));
#pragma unroll
            for (int pp = 0; pp < MPPW; pp++) {
                const float v = h128b[pp * 128 + t];
                om0[pp] = fmaf(v, w.x, om0[pp]);
                om1[pp] = fmaf(v, w.y, om1[pp]);
            }
        }
    }

    // shortcut: points @ sc_w + sc_b
    float or0[MPPW], or1[MPPW];
    {
        const float2 sb = __ldg((const float2*)(scb + c0));
#pragma unroll
        for (int pp = 0; pp < MPPW; pp++) { or0[pp] = sb.x; or1[pp] = sb.y; }
#pragma unroll 4
        for (int t = 0; t < CPN; t++) {
            const float2 w = __ldg((const float2*)(sc + t * 64 + c0));
#pragma unroll
            for (int pp = 0; pp < MPPW; pp++) {
                const float v = h67b[pp * 68 + t];
                or0[pp] = fmaf(v, w.x, or0[pp]);
                or1[pp] = fmaf(v, w.y, or1[pp]);
            }
        }
    }

#pragma unroll
    for (int pp = 0; pp < MPPW; pp++) {
        const int p = pbase + pp;
        *(float2*)&out[(size_t)p * 64 + c0] =
            make_float2(fmaxf(or0[pp] + om0[pp], 0.0f),
                        fmaxf(or1[pp] + om1[pp], 0.0f));
    }
}

// ============================================================================
extern "C" void kernel_launch(void* const* d_in, const int* in_sizes, int n_in,
                              void* d_out, int out_size) {
    const float* xyz    = (const float*)d_in[0];
    const float* points = (const float*)d_in[1];
    const float* w1     = (const float*)d_in[2];
    const float* b1     = (const float*)d_in[3];
    const float* w2     = (const float*)d_in[4];
    const float* b2     = (const float*)d_in[5];
    const float* m1     = (const float*)d_in[6];
    const float* mb1    = (const float*)d_in[7];
    const float* m2     = (const float*)d_in[8];
    const float* mb2    = (const float*)d_in[9];
    const float* sc     = (const float*)d_in[10];
    const float* scb    = (const float*)d_in[11];
    float* out = (float*)d_out;
    (void)in_sizes; (void)n_in; (void)out_size;

    grid_build<<<BB, 512>>>(xyz);
    knn_query<<<dim3(NN / 128, BB), 128>>>();

    cudaFuncSetAttribute(dfg_kernel,
                         cudaFuncAttributeMaxDynamicSharedMemorySize,
                         DSMEM_BYTES);
    dfg_kernel<<<BB * NN / (DW * DPPW), DTPB, DSMEM_BYTES>>>(
        xyz, points, w1, b1, w2, b2);

    cudaFuncSetAttribute(mlp_kernel,
                         cudaFuncAttributeMaxDynamicSharedMemorySize,
                         MSMEM_BYTES);
    mlp_kernel<<<BB * NN / (MW * MPPW), MTPB, MSMEM_BYTES>>>(
        points, m1, mb1, m2, mb2, sc, scb, out);
}